// round 2
// baseline (speedup 1.0000x reference)
#include <cuda_runtime.h>
#include <cuda_fp16.h>
#include <math.h>

#define TT 8
#define HH 64
#define WWD 64
#define CC 64
#define HWX (HH*WWD)            // 4096
#define PLANE (TT*HH*WWD)       // 32768
#define KTAP 27
#define KTOT (CC*KTAP)          // 1728

// -------- device scratch (no allocs allowed) --------
__device__ float g_y1[CC*PLANE];          // lrelu(conv1) output
__device__ float g_off[54*PLANE];         // offsets
__device__ float g_W1t[KTOT*64];          // transposed weights [kidx][o]
__device__ float g_Wofft[KTOT*64];
__device__ float g_Wdt[KTOT*64];
__device__ float g_Wrt[64*64];            // [c][o]

// -------- weight transpose / pad --------
__global__ void prep_weights(const float* __restrict__ W1, const float* __restrict__ Woff,
                             const float* __restrict__ Wd, const float* __restrict__ Wr) {
    int i = blockIdx.x*256 + threadIdx.x;
    if (i < KTOT*64) {
        int kidx = i >> 6, o = i & 63;
        g_W1t[i]  = W1[o*KTOT + kidx];
        g_Wdt[i]  = Wd[o*KTOT + kidx];
        g_Wofft[i] = (o < 54) ? Woff[o*KTOT + kidx] : 0.f;
        if (i < 64*64) {
            int c = i >> 6, oo = i & 63;
            g_Wrt[i] = Wr[oo*64 + c];
        }
    }
}

// -------- 3x3x3 conv as implicit GEMM, N=128 (two h rows) --------
// grid 256 = T * H/2 ; block 256 threads ; tile 8x4 per thread
__global__ void __launch_bounds__(256, 3)
conv3x3x3_kernel(const float* __restrict__ src, const float* __restrict__ Wt,
                 const float* __restrict__ bias, float* __restrict__ dst,
                 int oc_count, int do_lrelu)
{
    __shared__ float sA[8*64];
    __shared__ float sB[8*128];
    __shared__ unsigned short sDec[KTOT];   // (c<<5)|k

    int tid = threadIdx.x;
    int t  = blockIdx.x >> 5;
    int h0 = (blockIdx.x & 31) << 1;

    for (int e = tid; e < KTOT; e += 256) {
        int c = e / 27;
        int k = e - c*27;
        sDec[e] = (unsigned short)((c<<5) | k);
    }
    __syncthreads();

    int tx = tid & 31, ty = tid >> 5;       // n0 = tx*4, m0 = ty*8
    float acc[8][4];
    #pragma unroll
    for (int i=0;i<8;i++)
        #pragma unroll
        for (int j=0;j<4;j++) acc[i][j]=0.f;

    for (int kk = 0; kk < KTOT; kk += 8) {
        // stage A: weights [kc][o]  (512 elems, 2/thread)
        #pragma unroll
        for (int i = 0; i < 2; i++) {
            int e = tid + i*256;
            sA[e] = Wt[(kk + (e>>6))*64 + (e & 63)];
        }
        // stage B: im2col [kc][n]   (1024 elems, 4/thread)
        #pragma unroll
        for (int i = 0; i < 4; i++) {
            int e = tid + i*256;
            int kc = e >> 7, n = e & 127;
            int hh = n >> 6, w = n & 63;
            unsigned int d = sDec[kk+kc];
            int c = d >> 5;
            int k = d & 31;
            int kt = k / 9; int r = k - kt*9;
            int kh = r / 3; int kw = r - kh*3;
            int t_in = t - 1 + kt;
            int h_in = h0 + hh - 1 + kh;
            int w_in = w - 1 + kw;
            float v = 0.f;
            if ((unsigned)t_in < TT && (unsigned)h_in < HH && (unsigned)w_in < WWD)
                v = src[c*PLANE + t_in*HWX + h_in*WWD + w_in];
            sB[e] = v;
        }
        __syncthreads();
        #pragma unroll
        for (int kc = 0; kc < 8; kc++) {
            float4 a0 = *(const float4*)&sA[kc*64 + ty*8];
            float4 a1 = *(const float4*)&sA[kc*64 + ty*8 + 4];
            float4 b  = *(const float4*)&sB[kc*128 + tx*4];
            float av[8] = {a0.x,a0.y,a0.z,a0.w,a1.x,a1.y,a1.z,a1.w};
            float bv[4] = {b.x,b.y,b.z,b.w};
            #pragma unroll
            for (int i=0;i<8;i++)
                #pragma unroll
                for (int j=0;j<4;j++)
                    acc[i][j] = fmaf(av[i], bv[j], acc[i][j]);
        }
        __syncthreads();
    }

    int base = t*HWX + h0*WWD + tx*4;
    #pragma unroll
    for (int i=0;i<8;i++) {
        int o = ty*8 + i;
        if (o < oc_count) {
            float bvv = bias[o];
            float4 r;
            float v0 = acc[i][0] + bvv;
            float v1 = acc[i][1] + bvv;
            float v2 = acc[i][2] + bvv;
            float v3 = acc[i][3] + bvv;
            if (do_lrelu) {
                v0 = v0 >= 0.f ? v0 : 0.01f*v0;
                v1 = v1 >= 0.f ? v1 : 0.01f*v1;
                v2 = v2 >= 0.f ? v2 : 0.01f*v2;
                v3 = v3 >= 0.f ? v3 : 0.01f*v3;
            }
            r.x = v0; r.y = v1; r.z = v2; r.w = v3;
            *(float4*)&dst[o*PLANE + base] = r;
        }
    }
}

// -------- deformable conv + residual + lrelu, fused, N=128 --------
// dyn smem layout (bytes):
//   sA    [0,      2048)   8*64 f
//   sB    [2048,   6144)   8*128 f
//   sOff  [6144,  33792)   27*128 ushort4
//   sWtH  [33792, 61440)   27*128*2 __half2
//   sDec  [61440, 64896)   1728 ushort
__global__ void __launch_bounds__(256, 3)
deform_kernel(const float* __restrict__ x, const float* __restrict__ bd,
              const float* __restrict__ br, float* __restrict__ out)
{
    extern __shared__ char smraw[];
    float*   sA   = (float*)smraw;
    float*   sB   = (float*)(smraw + 2048);
    ushort4* sOff = (ushort4*)(smraw + 6144);
    __half2* sWtH = (__half2*)(smraw + 33792);
    unsigned short* sDec = (unsigned short*)(smraw + 61440);

    int tid = threadIdx.x;
    int t  = blockIdx.x >> 5;
    int h0 = (blockIdx.x & 31) << 1;

    for (int e = tid; e < KTOT; e += 256) {
        int c = e / 27;
        int k = e - c*27;
        sDec[e] = (unsigned short)((c<<5) | k);
    }

    // precompute bilinear taps per (k, n): reused by all 64 channels
    for (int e = tid; e < KTAP*128; e += 256) {
        int k = e >> 7, n = e & 127;
        int hh = n >> 6, w = n & 63;
        int h = h0 + hh;
        int kt = k / 9; int r = k - kt*9;
        int kh = r / 3; int kw = r - kh*3;
        int t_in = t - 1 + kt;
        bool t_ok = ((unsigned)t_in < TT);
        int t_c = min(max(t_in,0),TT-1);
        int pidx = t*HWX + h*WWD + w;
        float dh = g_off[(2*k)*PLANE + pidx];
        float dw = g_off[(2*k+1)*PLANE + pidx];
        float h_s = (float)(h - 1 + kh) + dh;
        float w_s = (float)(w - 1 + kw) + dw;
        float h0f = floorf(h_s), w0f = floorf(w_s);
        float fh = h_s - h0f,  fw = w_s - w0f;
        int hb = (int)h0f, wb = (int)w0f;
        int tb = t_c*HWX;
        float wgt[4];
        unsigned short ofs[4];
        #pragma unroll
        for (int q = 0; q < 4; q++) {
            int ih = hb + (q >> 1), iw = wb + (q & 1);
            bool ok = t_ok && ((unsigned)ih < HH) && ((unsigned)iw < WWD);
            int ihc = min(max(ih,0),HH-1), iwc = min(max(iw,0),WWD-1);
            float whv = (q >> 1) ? fh : 1.f - fh;
            float wvv = (q & 1)  ? fw : 1.f - fw;
            wgt[q] = ok ? whv*wvv : 0.f;
            ofs[q] = (unsigned short)(tb + ihc*WWD + iwc);
        }
        sWtH[e*2]   = __floats2half2_rn(wgt[0], wgt[1]);
        sWtH[e*2+1] = __floats2half2_rn(wgt[2], wgt[3]);
        sOff[e] = make_ushort4(ofs[0], ofs[1], ofs[2], ofs[3]);
    }
    __syncthreads();

    int tx = tid & 31, ty = tid >> 5;
    float acc[8][4];
    #pragma unroll
    for (int i=0;i<8;i++)
        #pragma unroll
        for (int j=0;j<4;j++) acc[i][j]=0.f;

    // main deformable GEMM: K = 1728
    for (int kk = 0; kk < KTOT; kk += 8) {
        #pragma unroll
        for (int i = 0; i < 2; i++) {
            int e = tid + i*256;
            sA[e] = g_Wdt[(kk + (e>>6))*64 + (e & 63)];
        }
        #pragma unroll
        for (int i = 0; i < 4; i++) {
            int e = tid + i*256;
            int kc = e >> 7, n = e & 127;
            unsigned int d = sDec[kk+kc];
            int c = d >> 5;
            int k = d & 31;
            int ew = (k << 7) + n;
            const float* yc = g_y1 + c*PLANE;
            ushort4 of = sOff[ew];
            float2 w01 = __half22float2(sWtH[ew*2]);
            float2 w23 = __half22float2(sWtH[ew*2+1]);
            float v = w01.x*yc[of.x] + w01.y*yc[of.y]
                    + w23.x*yc[of.z] + w23.y*yc[of.w];
            sB[e] = v;
        }
        __syncthreads();
        #pragma unroll
        for (int kc = 0; kc < 8; kc++) {
            float4 a0 = *(const float4*)&sA[kc*64 + ty*8];
            float4 a1 = *(const float4*)&sA[kc*64 + ty*8 + 4];
            float4 b  = *(const float4*)&sB[kc*128 + tx*4];
            float av[8] = {a0.x,a0.y,a0.z,a0.w,a1.x,a1.y,a1.z,a1.w};
            float bv[4] = {b.x,b.y,b.z,b.w};
            #pragma unroll
            for (int i=0;i<8;i++)
                #pragma unroll
                for (int j=0;j<4;j++)
                    acc[i][j] = fmaf(av[i], bv[j], acc[i][j]);
        }
        __syncthreads();
    }

    // fold lrelu+bias into acc, then accumulate residual into same regs
    #pragma unroll
    for (int i=0;i<8;i++) {
        int o = ty*8 + i;
        float bdv = bd[o], brv = br[o];
        #pragma unroll
        for (int j=0;j<4;j++) {
            float vd = acc[i][j] + bdv;
            vd = vd >= 0.f ? vd : 0.01f*vd;
            acc[i][j] = vd + brv;
        }
    }

    // residual 1x1 GEMM: K = 64
    int base_p = t*HWX + h0*WWD;
    for (int kk = 0; kk < 64; kk += 8) {
        #pragma unroll
        for (int i = 0; i < 2; i++) {
            int e = tid + i*256;
            sA[e] = g_Wrt[(kk + (e>>6))*64 + (e & 63)];
        }
        #pragma unroll
        for (int i = 0; i < 4; i++) {
            int e = tid + i*256;
            int kc = e >> 7, n = e & 127;
            sB[e] = x[(kk+kc)*PLANE + base_p + n];
        }
        __syncthreads();
        #pragma unroll
        for (int kc = 0; kc < 8; kc++) {
            float4 a0 = *(const float4*)&sA[kc*64 + ty*8];
            float4 a1 = *(const float4*)&sA[kc*64 + ty*8 + 4];
            float4 b  = *(const float4*)&sB[kc*128 + tx*4];
            float av[8] = {a0.x,a0.y,a0.z,a0.w,a1.x,a1.y,a1.z,a1.w};
            float bv[4] = {b.x,b.y,b.z,b.w};
            #pragma unroll
            for (int i=0;i<8;i++)
                #pragma unroll
                for (int j=0;j<4;j++)
                    acc[i][j] = fmaf(av[i], bv[j], acc[i][j]);
        }
        __syncthreads();
    }

    #pragma unroll
    for (int i=0;i<8;i++) {
        int o = ty*8 + i;
        float4 r;
        r.x = acc[i][0]; r.y = acc[i][1]; r.z = acc[i][2]; r.w = acc[i][3];
        *(float4*)&out[o*PLANE + base_p + tx*4] = r;
    }
}

// -------- launch --------
extern "C" void kernel_launch(void* const* d_in, const int* in_sizes, int n_in,
                              void* d_out, int out_size) {
    (void)in_sizes; (void)n_in; (void)out_size;
    const float* x    = (const float*)d_in[0];
    const float* W1   = (const float*)d_in[1];
    const float* b1   = (const float*)d_in[2];
    const float* Woff = (const float*)d_in[3];
    const float* boff = (const float*)d_in[4];
    const float* Wd   = (const float*)d_in[5];
    const float* bd   = (const float*)d_in[6];
    const float* Wr   = (const float*)d_in[7];
    const float* br   = (const float*)d_in[8];
    float* out = (float*)d_out;

    float *y1p, *offp, *W1tp, *Wofftp;
    cudaGetSymbolAddress((void**)&y1p, g_y1);
    cudaGetSymbolAddress((void**)&offp, g_off);
    cudaGetSymbolAddress((void**)&W1tp, g_W1t);
    cudaGetSymbolAddress((void**)&Wofftp, g_Wofft);

    const int SMEM_DEFORM = 64896;
    static int smem_set = 0;
    if (!smem_set) {
        cudaFuncSetAttribute(deform_kernel, cudaFuncAttributeMaxDynamicSharedMemorySize, SMEM_DEFORM);
        smem_set = 1;
    }

    prep_weights<<<(KTOT*64 + 255)/256, 256>>>(W1, Woff, Wd, Wr);
    conv3x3x3_kernel<<<256, 256>>>(x,   W1tp,   b1,   y1p,  64, 1);
    conv3x3x3_kernel<<<256, 256>>>(y1p, Wofftp, boff, offp, 54, 0);
    deform_kernel<<<256, 256, SMEM_DEFORM>>>(x, bd, br, out);
}

// round 4
// speedup vs baseline: 1.7894x; 1.7894x over previous
#include <cuda_runtime.h>
#include <cuda_fp16.h>
#include <cstdint>

#define TT 8
#define HH 64
#define WWD 64
#define HWX 4096
#define PLANE 32768
#define KTAP 27
#define KTOT 1728
#define PADW 34
#define OUTW 132

// -------- device scratch --------
__device__ float g_y1[64*PLANE];
__device__ float g_off[54*PLANE];
__device__ float g_W1t[KTOT*64];     // [k][o], tf32-rounded
__device__ float g_Wofft[KTOT*64];   // [k][o], zero-padded o>=54
__device__ float g_Wdt[KTOT*64];
__device__ float g_Wrt[64*64];       // [c][o]

__device__ __forceinline__ uint32_t f2tf32(float v){
    uint32_t r;
    asm("cvt.rna.tf32.f32 %0, %1;" : "=r"(r) : "f"(v));
    return r;
}
__device__ __forceinline__ void mma8(float* d, uint32_t a0, uint32_t a1, uint32_t a2, uint32_t a3,
                                     uint32_t b0, uint32_t b1){
    asm volatile("mma.sync.aligned.m16n8k8.row.col.f32.tf32.tf32.f32 "
        "{%0,%1,%2,%3}, {%4,%5,%6,%7}, {%8,%9}, {%0,%1,%2,%3};"
        : "+f"(d[0]), "+f"(d[1]), "+f"(d[2]), "+f"(d[3])
        : "r"(a0), "r"(a1), "r"(a2), "r"(a3), "r"(b0), "r"(b1));
}
// staged column for k_local (0..31) at row r: k-pair interleave + XOR swizzle
__device__ __forceinline__ int scol(int k, int r){
    return ((((k>>3) ^ (r&3))<<3) | ((k&3)<<1) | ((k>>2)&1));
}

// -------- weight transpose + tf32 quantize --------
__global__ void prep_weights(const float* __restrict__ W1, const float* __restrict__ Woff,
                             const float* __restrict__ Wd, const float* __restrict__ Wr) {
    int i = blockIdx.x*256 + threadIdx.x;
    if (i < KTOT*64) {
        int kidx = i >> 6, o = i & 63;
        g_W1t[i]  = __uint_as_float(f2tf32(W1[o*KTOT + kidx]));
        g_Wdt[i]  = __uint_as_float(f2tf32(Wd[o*KTOT + kidx]));
        g_Wofft[i] = (o < 54) ? __uint_as_float(f2tf32(Woff[o*KTOT + kidx])) : 0.f;
        if (i < 64*64) {
            int c = i >> 6, oo = i & 63;
            g_Wrt[i] = __uint_as_float(f2tf32(Wr[oo*64 + c]));
        }
    }
}

// ==================== conv 3x3x3 via mma.sync tf32 ====================
// smem: sBias 256 | sDec 3456 (at 256) | sA 128*34*4 (at 3712) | sB 64*34*4 | sOut 64*132*4 aliases sA
#define SMEM_CONV (3712 + 33792)
__global__ void __launch_bounds__(256)
conv_mma(const float* __restrict__ src, const float* __restrict__ Wt,
         const float* __restrict__ bias, float* __restrict__ dst,
         int oc_count, int do_lrelu)
{
    extern __shared__ char sm[];
    float* sBias = (float*)sm;
    unsigned short* sDec = (unsigned short*)(sm + 256);
    uint32_t* sA = (uint32_t*)(sm + 3712);
    uint32_t* sB = sA + 128*PADW;
    float* sOut = (float*)(sm + 3712);   // alias over sA+sB after GEMM

    int tid = threadIdx.x, wid = tid>>5, lane = tid&31;
    int t  = blockIdx.x >> 5;
    int h0 = (blockIdx.x & 31) << 1;

    for (int e = tid; e < KTOT; e += 256){
        int c = e/27, tap = e - c*27;
        int kt = tap/9, r = tap - kt*9, kh = r/3, kw = r - kh*3;
        sDec[e] = (unsigned short)((c<<6)|(kt<<4)|(kh<<2)|kw);
    }
    if (tid < 64) sBias[tid] = (tid < oc_count) ? bias[tid] : 0.f;
    __syncthreads();

    int n  = tid & 127, hh = n >> 6, w = n & 63;
    int jA0 = tid >> 7;
    int oB  = tid & 63, jB0 = tid >> 6;
    int q = lane >> 2, c2 = (lane & 3) << 1;
    int m0 = wid * 16;

    float acc[8][4];
    #pragma unroll
    for (int i=0;i<8;i++){ acc[i][0]=0.f; acc[i][1]=0.f; acc[i][2]=0.f; acc[i][3]=0.f; }

    for (int kk = 0; kk < KTOT; kk += 32){
        #pragma unroll 4
        for (int i = 0; i < 16; i++){
            int k = i*2 + jA0;
            unsigned d = sDec[kk + k];
            int c = d>>6, kt=(d>>4)&3, kh=(d>>2)&3, kw=d&3;
            int t_in = t-1+kt, h_in = h0+hh-1+kh, w_in = w-1+kw;
            float v = 0.f;
            if ((unsigned)t_in < TT && (unsigned)h_in < HH && (unsigned)w_in < WWD)
                v = src[c*PLANE + t_in*HWX + h_in*WWD + w_in];
            sA[n*PADW + scol(k, n)] = f2tf32(v);
        }
        #pragma unroll 4
        for (int i = 0; i < 8; i++){
            int k = i*4 + jB0;
            sB[oB*PADW + scol(k, oB)] = __float_as_uint(Wt[(kk+k)*64 + oB]);
        }
        __syncthreads();
        #pragma unroll
        for (int g = 0; g < 4; g++){
            int col = (((g ^ (q&3))<<3) | c2);
            uint2 a02 = *(uint2*)&sA[(m0+q)*PADW + col];
            uint2 a13 = *(uint2*)&sA[(m0+q+8)*PADW + col];
            #pragma unroll
            for (int nt = 0; nt < 8; nt++){
                uint2 b01 = *(uint2*)&sB[(nt*8+q)*PADW + col];
                mma8(acc[nt], a02.x, a13.x, a02.y, a13.y, b01.x, b01.y);
            }
        }
        __syncthreads();
    }

    // epilogue: bias + lrelu, transpose through smem, coalesced store
    #pragma unroll
    for (int nt = 0; nt < 8; nt++){
        int o = nt*8 + c2;
        int nn = m0 + q;
        float b0v = sBias[o], b1v = sBias[o+1];
        float v0 = acc[nt][0] + b0v, v1 = acc[nt][1] + b1v;
        float v2 = acc[nt][2] + b0v, v3 = acc[nt][3] + b1v;
        if (do_lrelu){
            v0 = v0>=0.f? v0 : 0.01f*v0; v1 = v1>=0.f? v1 : 0.01f*v1;
            v2 = v2>=0.f? v2 : 0.01f*v2; v3 = v3>=0.f? v3 : 0.01f*v3;
        }
        sOut[o*OUTW + nn]     = v0; sOut[(o+1)*OUTW + nn]     = v1;
        sOut[o*OUTW + nn + 8] = v2; sOut[(o+1)*OUTW + nn + 8] = v3;
    }
    __syncthreads();
    int base = t*HWX + h0*WWD;
    int n4 = (tid & 31) * 4;
    #pragma unroll
    for (int i = 0; i < 8; i++){
        int o = (tid>>5) + i*8;
        float4 v = *(float4*)&sOut[o*OUTW + n4];
        if (o < oc_count) *(float4*)&dst[o*PLANE + base + n4] = v;
    }
}

// ==================== deformable conv + residual + lrelu ====================
// smem: sBd 256 | sBr 256 | sDec 3456 (at 512) | sA at 4096 (17408) | sB (8704) at 21504 |
//       sOff 27648 at 30208 | sWt 27648 at 57856 | total 85504 ; sOut aliases sA (at 4096)
#define SMEM_DEF 85504
__global__ void __launch_bounds__(256)
deform_mma(const float* __restrict__ x, const float* __restrict__ bd,
           const float* __restrict__ br, float* __restrict__ out)
{
    extern __shared__ char sm[];
    float* sBd = (float*)sm;
    float* sBr = (float*)(sm + 256);
    unsigned short* sDec = (unsigned short*)(sm + 512);
    uint32_t* sA = (uint32_t*)(sm + 4096);
    uint32_t* sB = sA + 128*PADW;
    ushort4* sOff = (ushort4*)(sm + 30208);
    __half2* sWt  = (__half2*)(sm + 57856);
    float* sOut = (float*)(sm + 4096);

    int tid = threadIdx.x, wid = tid>>5, lane = tid&31;
    int t  = blockIdx.x >> 5;
    int h0 = (blockIdx.x & 31) << 1;

    for (int e = tid; e < KTOT; e += 256){
        int c = e/27, tap = e - c*27;
        sDec[e] = (unsigned short)((c<<5) | tap);
    }
    if (tid < 64){ sBd[tid] = bd[tid]; sBr[tid] = br[tid]; }

    // bilinear tap tables: computed once, reused by all 64 channels
    for (int e = tid; e < KTAP*128; e += 256){
        int k = e >> 7, n = e & 127;
        int hh = n >> 6, w = n & 63;
        int h = h0 + hh;
        int kt = k/9, r = k - kt*9, kh = r/3, kw = r - kh*3;
        int t_in = t - 1 + kt;
        bool t_ok = ((unsigned)t_in < TT);
        int t_c = min(max(t_in,0),TT-1);
        int pidx = t*HWX + h*WWD + w;
        float dh = g_off[(2*k)*PLANE + pidx];
        float dw = g_off[(2*k+1)*PLANE + pidx];
        float h_s = (float)(h - 1 + kh) + dh;
        float w_s = (float)(w - 1 + kw) + dw;
        float h0f = floorf(h_s), w0f = floorf(w_s);
        float fh = h_s - h0f, fw = w_s - w0f;
        int hb = (int)h0f, wb = (int)w0f;
        int tb = t_c*HWX;
        float wgt[4]; unsigned short ofs[4];
        #pragma unroll
        for (int qq = 0; qq < 4; qq++){
            int ih = hb + (qq>>1), iw = wb + (qq&1);
            bool ok = t_ok && ((unsigned)ih < HH) && ((unsigned)iw < WWD);
            int ihc = min(max(ih,0),HH-1), iwc = min(max(iw,0),WWD-1);
            float whv = (qq>>1) ? fh : 1.f - fh;
            float wvv = (qq&1)  ? fw : 1.f - fw;
            wgt[qq] = ok ? whv*wvv : 0.f;
            ofs[qq] = (unsigned short)(tb + ihc*WWD + iwc);
        }
        sWt[e*2]   = __floats2half2_rn(wgt[0], wgt[1]);
        sWt[e*2+1] = __floats2half2_rn(wgt[2], wgt[3]);
        sOff[e] = make_ushort4(ofs[0], ofs[1], ofs[2], ofs[3]);
    }
    __syncthreads();

    int n  = tid & 127;
    int jA0 = tid >> 7;
    int oB  = tid & 63, jB0 = tid >> 6;
    int q = lane >> 2, c2 = (lane & 3) << 1;
    int m0 = wid * 16;
    int base_p = t*HWX + h0*WWD;

    float acc[8][4];
    #pragma unroll
    for (int i=0;i<8;i++){ acc[i][0]=0.f; acc[i][1]=0.f; acc[i][2]=0.f; acc[i][3]=0.f; }

    // main deformable GEMM: K = 1728
    for (int kk = 0; kk < KTOT; kk += 32){
        #pragma unroll 4
        for (int i = 0; i < 16; i++){
            int k = i*2 + jA0;
            unsigned d = sDec[kk + k];
            int c = d >> 5, tap = d & 31;
            int te = tap*128 + n;
            ushort4 of = sOff[te];
            float2 f01 = __half22float2(sWt[2*te]);
            float2 f23 = __half22float2(sWt[2*te+1]);
            const float* yc = g_y1 + c*PLANE;
            float v = f01.x*yc[of.x] + f01.y*yc[of.y]
                    + f23.x*yc[of.z] + f23.y*yc[of.w];
            sA[n*PADW + scol(k, n)] = f2tf32(v);
        }
        #pragma unroll 4
        for (int i = 0; i < 8; i++){
            int k = i*4 + jB0;
            sB[oB*PADW + scol(k, oB)] = __float_as_uint(g_Wdt[(kk+k)*64 + oB]);
        }
        __syncthreads();
        #pragma unroll
        for (int g = 0; g < 4; g++){
            int col = (((g ^ (q&3))<<3) | c2);
            uint2 a02 = *(uint2*)&sA[(m0+q)*PADW + col];
            uint2 a13 = *(uint2*)&sA[(m0+q+8)*PADW + col];
            #pragma unroll
            for (int nt = 0; nt < 8; nt++){
                uint2 b01 = *(uint2*)&sB[(nt*8+q)*PADW + col];
                mma8(acc[nt], a02.x, a13.x, a02.y, a13.y, b01.x, b01.y);
            }
        }
        __syncthreads();
    }

    // fold bias + lrelu into acc, keep accumulating residual into same regs
    #pragma unroll
    for (int nt = 0; nt < 8; nt++){
        int o = nt*8 + c2;
        float b0v = sBd[o], b1v = sBd[o+1];
        float v;
        v = acc[nt][0] + b0v; acc[nt][0] = v>=0.f? v : 0.01f*v;
        v = acc[nt][1] + b1v; acc[nt][1] = v>=0.f? v : 0.01f*v;
        v = acc[nt][2] + b0v; acc[nt][2] = v>=0.f? v : 0.01f*v;
        v = acc[nt][3] + b1v; acc[nt][3] = v>=0.f? v : 0.01f*v;
    }

    // residual 1x1 GEMM: K = 64 (2 chunks)
    for (int kk = 0; kk < 64; kk += 32){
        #pragma unroll 4
        for (int i = 0; i < 16; i++){
            int k = i*2 + jA0;
            float v = x[(kk+k)*PLANE + base_p + n];
            sA[n*PADW + scol(k, n)] = f2tf32(v);
        }
        #pragma unroll 4
        for (int i = 0; i < 8; i++){
            int k = i*4 + jB0;
            sB[oB*PADW + scol(k, oB)] = __float_as_uint(g_Wrt[(kk+k)*64 + oB]);
        }
        __syncthreads();
        #pragma unroll
        for (int g = 0; g < 4; g++){
            int col = (((g ^ (q&3))<<3) | c2);
            uint2 a02 = *(uint2*)&sA[(m0+q)*PADW + col];
            uint2 a13 = *(uint2*)&sA[(m0+q+8)*PADW + col];
            #pragma unroll
            for (int nt = 0; nt < 8; nt++){
                uint2 b01 = *(uint2*)&sB[(nt*8+q)*PADW + col];
                mma8(acc[nt], a02.x, a13.x, a02.y, a13.y, b01.x, b01.y);
            }
        }
        __syncthreads();
    }

    // epilogue: + br, transpose, coalesced store
    #pragma unroll
    for (int nt = 0; nt < 8; nt++){
        int o = nt*8 + c2;
        int nn = m0 + q;
        float b0v = sBr[o], b1v = sBr[o+1];
        sOut[o*OUTW + nn]     = acc[nt][0] + b0v;
        sOut[(o+1)*OUTW + nn] = acc[nt][1] + b1v;
        sOut[o*OUTW + nn + 8]     = acc[nt][2] + b0v;
        sOut[(o+1)*OUTW + nn + 8] = acc[nt][3] + b1v;
    }
    __syncthreads();
    int n4 = (tid & 31) * 4;
    #pragma unroll
    for (int i = 0; i < 8; i++){
        int o = (tid>>5) + i*8;
        float4 v = *(float4*)&sOut[o*OUTW + n4];
        *(float4*)&out[o*PLANE + base_p + n4] = v;
    }
}

// -------- launch --------
extern "C" void kernel_launch(void* const* d_in, const int* in_sizes, int n_in,
                              void* d_out, int out_size) {
    (void)in_sizes; (void)n_in; (void)out_size;
    const float* x    = (const float*)d_in[0];
    const float* W1   = (const float*)d_in[1];
    const float* b1   = (const float*)d_in[2];
    const float* Woff = (const float*)d_in[3];
    const float* boff = (const float*)d_in[4];
    const float* Wd   = (const float*)d_in[5];
    const float* bd   = (const float*)d_in[6];
    const float* Wr   = (const float*)d_in[7];
    const float* br   = (const float*)d_in[8];
    float* out = (float*)d_out;

    float *y1p, *offp, *W1tp, *Wofftp;
    cudaGetSymbolAddress((void**)&y1p, g_y1);
    cudaGetSymbolAddress((void**)&offp, g_off);
    cudaGetSymbolAddress((void**)&W1tp, g_W1t);
    cudaGetSymbolAddress((void**)&Wofftp, g_Wofft);

    cudaFuncSetAttribute(conv_mma,   cudaFuncAttributeMaxDynamicSharedMemorySize, SMEM_CONV);
    cudaFuncSetAttribute(deform_mma, cudaFuncAttributeMaxDynamicSharedMemorySize, SMEM_DEF);

    prep_weights<<<(KTOT*64 + 255)/256, 256>>>(W1, Woff, Wd, Wr);
    conv_mma<<<256, 256, SMEM_CONV>>>(x,   W1tp,   b1,   y1p,  64, 1);
    conv_mma<<<256, 256, SMEM_CONV>>>(y1p, Wofftp, boff, offp, 54, 0);
    deform_mma<<<256, 256, SMEM_DEF>>>(x, bd, br, out);
}

// round 5
// speedup vs baseline: 6.0796x; 3.3976x over previous
#include <cuda_runtime.h>
#include <cuda_fp16.h>
#include <cstdint>

#define TT 8
#define HH 64
#define WWD 64
#define HWX 4096
#define PLANE 32768
#define KTAP 27

// -------- device scratch --------
__device__ __half g_y1h[64*PLANE];       // lrelu(conv1), fp16, [c][pos]
__device__ float  g_off[54*PLANE];       // offsets fp32
__device__ __half g_W1h[KTAP*64*64];     // [tap][o][c]
__device__ __half g_Woffh[KTAP*64*64];   // [tap][o][c], o>=54 zero
__device__ __half g_Wdh[KTAP*64*64];
__device__ __half g_Wrh[64*64];          // [o][c]

__device__ __forceinline__ uint32_t smem_u32(const void* p){
    uint32_t a;
    asm("{ .reg .u64 t; cvta.to.shared.u64 t, %1; cvt.u32.u64 %0, t; }"
        : "=r"(a) : "l"(p));
    return a;
}
__device__ __forceinline__ void ldsm4(uint32_t& r0,uint32_t& r1,uint32_t& r2,uint32_t& r3, uint32_t addr){
    asm volatile("ldmatrix.sync.aligned.m8n8.x4.shared.b16 {%0,%1,%2,%3}, [%4];"
        : "=r"(r0),"=r"(r1),"=r"(r2),"=r"(r3) : "r"(addr));
}
__device__ __forceinline__ void mma16816(float* d, uint32_t a0,uint32_t a1,uint32_t a2,uint32_t a3,
                                         uint32_t b0,uint32_t b1){
    asm volatile("mma.sync.aligned.m16n8k16.row.col.f32.f16.f16.f32 "
        "{%0,%1,%2,%3},{%4,%5,%6,%7},{%8,%9},{%0,%1,%2,%3};"
        : "+f"(d[0]),"+f"(d[1]),"+f"(d[2]),"+f"(d[3])
        : "r"(a0),"r"(a1),"r"(a2),"r"(a3),"r"(b0),"r"(b1));
}

// one K=64 chunk of the block GEMM: A[128x64h] x B[64x64h]^T -> acc
__device__ __forceinline__ void gemm_chunk(uint32_t Ab, uint32_t Bb, int m0, int lane, float acc[8][4]){
    int g = lane>>3, r = lane&7;
    #pragma unroll
    for (int st=0; st<4; st++){
        int rowA = m0 + (g&1)*8 + r;
        int segA = st*2 + (g>>1);
        uint32_t a0,a1,a2,a3;
        ldsm4(a0,a1,a2,a3, Ab + rowA*128 + (((segA ^ (rowA&7)))<<4));
        #pragma unroll
        for (int p=0;p<4;p++){
            int rowB = p*16 + (g>>1)*8 + r;
            int segB = st*2 + (g&1);
            uint32_t b0,b1,b2,b3;
            ldsm4(b0,b1,b2,b3, Bb + rowB*128 + (((segB ^ (rowB&7)))<<4));
            mma16816(acc[2*p],   a0,a1,a2,a3, b0,b1);
            mma16816(acc[2*p+1], a0,a1,a2,a3, b2,b3);
        }
    }
}

// -------- weight repack to [tap][o][c] fp16 --------
__global__ void prep_weights(const float* __restrict__ W1, const float* __restrict__ Woff,
                             const float* __restrict__ Wd, const float* __restrict__ Wr){
    int i = blockIdx.x*256 + threadIdx.x;
    if (i < KTAP*64*64){
        int tap = i>>12, o = (i>>6)&63, c = i&63;
        int src = o*1728 + c*27 + tap;
        g_W1h[i] = __float2half(W1[src]);
        g_Wdh[i] = __float2half(Wd[src]);
        g_Woffh[i] = (o < 54) ? __float2half(Woff[src]) : __half(0.f);
        if (i < 64*64) g_Wrh[i] = __float2half(Wr[i]);
    }
}

// ==================== conv 3x3x3, fp16 mma ====================
// MODE 0: x(fp32) -> y1h(fp16), lrelu ; MODE 1: y1h -> g_off(fp32), 54 ch
#define SMEM_CONV 34816
template<int MODE>
__global__ void __launch_bounds__(256,3)
conv_f16(const float* __restrict__ xf, const float* __restrict__ bias)
{
    extern __shared__ char sm[];
    float* sBias = (float*)sm;
    char* SA = sm + 1024;
    char* SB = sm + 17408;
    uint32_t sbase = smem_u32(sm);
    uint32_t Ab = sbase + 1024, Bb = sbase + 17408;

    int tid = threadIdx.x, lane = tid&31, wid = tid>>5;
    int t = blockIdx.x>>5, h0 = (blockIdx.x&31)<<1;
    if (tid < 64) sBias[tid] = (MODE==0 || tid<54) ? bias[tid] : 0.f;
    __syncthreads();

    int n = tid&127, cg = tid>>7;
    int hh = n>>6, w = n&63;
    int m0 = wid*16;
    float acc[8][4];
    #pragma unroll
    for (int i=0;i<8;i++){ acc[i][0]=0.f; acc[i][1]=0.f; acc[i][2]=0.f; acc[i][3]=0.f; }

    const __half* Wall = (MODE==0) ? g_W1h : g_Woffh;

    for (int tap=0; tap<KTAP; tap++){
        int kt = tap/9, rr = tap-kt*9, kh = rr/3, kw = rr-kh*3;
        int t_in = t-1+kt, h_in = h0+hh-1+kh, w_in = w-1+kw;
        bool valid = ((unsigned)t_in<TT)&&((unsigned)h_in<HH)&&((unsigned)w_in<WWD);
        int pos = valid ? (t_in*HWX + h_in*WWD + w_in) : 0;
        #pragma unroll
        for (int g2=0; g2<4; g2++){
            union{ __half h[8]; uint4 u; } buf;
            #pragma unroll
            for (int j=0;j<8;j++){
                int c = cg*32 + g2*8 + j;
                if (MODE==0){
                    float v = valid ? __ldg(xf + c*PLANE + pos) : 0.f;
                    buf.h[j] = __float2half(v);
                } else {
                    buf.h[j] = valid ? g_y1h[c*PLANE + pos] : __half(0.f);
                }
            }
            int seg = cg*4 + g2;
            *(uint4*)(SA + n*128 + ((seg ^ (n&7))<<4)) = buf.u;
        }
        {
            int o = tid>>2, part = tid&3;
            const uint4* srcp = (const uint4*)(Wall + tap*4096 + o*64 + part*16);
            uint4 v0 = srcp[0], v1 = srcp[1];
            int s0 = part*2;
            *(uint4*)(SB + o*128 + ((s0 ^ (o&7))<<4)) = v0;
            *(uint4*)(SB + o*128 + (((s0+1) ^ (o&7))<<4)) = v1;
        }
        __syncthreads();
        gemm_chunk(Ab, Bb, m0, lane, acc);
        __syncthreads();
    }

    int q = lane>>2, c2 = (lane&3)<<1;
    int base = t*HWX + h0*WWD;
    if (MODE==0){
        __half* sOut = (__half*)(sm + 1024);   // rows of 136 halves
        #pragma unroll
        for (int nt=0;nt<8;nt++){
            int o = nt*8 + c2, nn = m0+q;
            float b0v = sBias[o], b1v = sBias[o+1];
            float v0 = acc[nt][0]+b0v, v1 = acc[nt][1]+b1v;
            float v2 = acc[nt][2]+b0v, v3 = acc[nt][3]+b1v;
            v0 = v0>=0.f?v0:0.01f*v0; v1 = v1>=0.f?v1:0.01f*v1;
            v2 = v2>=0.f?v2:0.01f*v2; v3 = v3>=0.f?v3:0.01f*v3;
            sOut[o*136+nn]       = __float2half(v0);
            sOut[(o+1)*136+nn]   = __float2half(v1);
            sOut[o*136+nn+8]     = __float2half(v2);
            sOut[(o+1)*136+nn+8] = __float2half(v3);
        }
        __syncthreads();
        int o = tid>>2, nq = (tid&3)*32;
        #pragma unroll
        for (int j=0;j<4;j++){
            uint4 v = *(uint4*)(sOut + o*136 + nq + j*8);
            *(uint4*)(g_y1h + o*PLANE + base + nq + j*8) = v;
        }
    } else {
        float* sOut = (float*)(sm + 1024);     // rows of 132 floats
        #pragma unroll
        for (int nt=0;nt<8;nt++){
            int o = nt*8 + c2, nn = m0+q;
            float b0v = sBias[o], b1v = sBias[o+1];
            sOut[o*132+nn]       = acc[nt][0]+b0v;
            sOut[(o+1)*132+nn]   = acc[nt][1]+b1v;
            sOut[o*132+nn+8]     = acc[nt][2]+b0v;
            sOut[(o+1)*132+nn+8] = acc[nt][3]+b1v;
        }
        __syncthreads();
        int n4 = (tid&31)*4;
        #pragma unroll
        for (int i=0;i<8;i++){
            int o = (tid>>5) + i*8;
            if (o < 54){
                float4 v = *(float4*)&sOut[o*132+n4];
                *(float4*)&g_off[o*PLANE + base + n4] = v;
            }
        }
    }
}

// ==================== deformable conv + residual + lrelu, fp16 mma ====================
// smem: misc[0,1024) | A[1024,17408) | B[17408,25600) | tab[25600,53248) ; fp32 out aliases A/B
#define SMEM_DEF 53248
__global__ void __launch_bounds__(256,3)
deform_f16(const float* __restrict__ xf, const float* __restrict__ bd,
           const float* __restrict__ br, float* __restrict__ out)
{
    extern __shared__ char sm[];
    float* sBd = (float*)sm;
    float* sBr = (float*)(sm + 256);
    char* SA = sm + 1024;
    char* SB = sm + 17408;
    uint2* sTab = (uint2*)(sm + 25600);
    uint32_t sbase = smem_u32(sm);
    uint32_t Ab = sbase + 1024, Bb = sbase + 17408;

    int tid = threadIdx.x, lane = tid&31, wid = tid>>5;
    int t = blockIdx.x>>5, h0 = (blockIdx.x&31)<<1;
    if (tid < 64){ sBd[tid] = bd[tid]; sBr[tid] = br[tid]; }

    // build packed bilinear tap table: 8B per (tap, n)
    for (int e = tid; e < KTAP*128; e += 256){
        int tap = e>>7, n = e&127;
        int hh = n>>6, w = n&63;
        int h = h0 + hh;
        int kt = tap/9, rr = tap-kt*9, kh = rr/3, kw = rr-kh*3;
        int t_in = t-1+kt;
        bool t_ok = (unsigned)t_in < TT;
        int t_c = min(max(t_in,0),TT-1);
        int pidx = t*HWX + h*WWD + w;
        float dh = g_off[(2*tap)*PLANE + pidx];
        float dw = g_off[(2*tap+1)*PLANE + pidx];
        float h_s = (float)(h-1+kh)+dh, w_s = (float)(w-1+kw)+dw;
        float h0f = floorf(h_s), w0f = floorf(w_s);
        float fh = h_s-h0f, fw = w_s-w0f;
        int hb = (int)h0f, wb = (int)w0f;
        unsigned mask = 0;
        if (t_ok){
            unsigned h0ok = ((unsigned)hb < HH),  h1ok = ((unsigned)(hb+1) < HH);
            unsigned w0ok = ((unsigned)wb < WWD), w1ok = ((unsigned)(wb+1) < WWD);
            mask = (h0ok&w0ok) | ((h0ok&w1ok)<<1) | ((h1ok&w0ok)<<2) | ((h1ok&w1ok)<<3);
        }
        int hbc = min(max(hb,-2),64), wbc = min(max(wb,-2),64);
        uint32_t pack = (uint32_t)(wbc+2) | ((uint32_t)(hbc+2)<<7) | ((uint32_t)t_c<<14) | (mask<<17);
        __half2 f2 = __floats2half2_rn(fh, fw);
        sTab[e] = make_uint2(pack, *(uint32_t*)&f2);
    }
    __syncthreads();

    int n = tid&127, cg = tid>>7;
    int m0 = wid*16;
    int base_p = t*HWX + h0*WWD;
    float acc[8][4];
    #pragma unroll
    for (int i=0;i<8;i++){ acc[i][0]=0.f; acc[i][1]=0.f; acc[i][2]=0.f; acc[i][3]=0.f; }

    // main deformable GEMM: 27 taps x 64 ch
    for (int tap=0; tap<KTAP; tap++){
        uint2 tb = sTab[tap*128 + n];
        uint32_t pk = tb.x;
        __half2 fhw = *(__half2*)&tb.y;
        float fh = __low2float(fhw), fw = __high2float(fhw);
        int wb = (int)(pk&127) - 2, hb = (int)((pk>>7)&127) - 2;
        int tc = (int)((pk>>14)&7);
        unsigned mask = pk>>17;
        float w00 = (1.f-fh)*(1.f-fw), w01 = (1.f-fh)*fw;
        float w10 = fh*(1.f-fw),       w11 = fh*fw;
        if (!(mask&1u)) w00 = 0.f;
        if (!(mask&2u)) w01 = 0.f;
        if (!(mask&4u)) w10 = 0.f;
        if (!(mask&8u)) w11 = 0.f;
        int ih0 = min(max(hb,0),HH-1),   ih1 = min(max(hb+1,0),HH-1);
        int iw0 = min(max(wb,0),WWD-1),  iw1 = min(max(wb+1,0),WWD-1);
        int tb0 = tc*HWX;
        const __half* p00 = g_y1h + cg*32*PLANE + tb0 + ih0*WWD + iw0;
        const __half* p01 = g_y1h + cg*32*PLANE + tb0 + ih0*WWD + iw1;
        const __half* p10 = g_y1h + cg*32*PLANE + tb0 + ih1*WWD + iw0;
        const __half* p11 = g_y1h + cg*32*PLANE + tb0 + ih1*WWD + iw1;
        #pragma unroll
        for (int g2=0; g2<4; g2++){
            union{ __half h[8]; uint4 u; } buf;
            #pragma unroll
            for (int j=0;j<8;j++){
                int coff = (g2*8+j)*PLANE;
                float f0 = __half2float(__ldg(p00 + coff));
                float f1 = __half2float(__ldg(p01 + coff));
                float f2v = __half2float(__ldg(p10 + coff));
                float f3 = __half2float(__ldg(p11 + coff));
                buf.h[j] = __float2half(w00*f0 + w01*f1 + w10*f2v + w11*f3);
            }
            int seg = cg*4 + g2;
            *(uint4*)(SA + n*128 + ((seg ^ (n&7))<<4)) = buf.u;
        }
        {
            int o = tid>>2, part = tid&3;
            const uint4* srcp = (const uint4*)(g_Wdh + tap*4096 + o*64 + part*16);
            uint4 v0 = srcp[0], v1 = srcp[1];
            int s0 = part*2;
            *(uint4*)(SB + o*128 + ((s0 ^ (o&7))<<4)) = v0;
            *(uint4*)(SB + o*128 + (((s0+1) ^ (o&7))<<4)) = v1;
        }
        __syncthreads();
        gemm_chunk(Ab, Bb, m0, lane, acc);
        __syncthreads();
    }

    int q = lane>>2, c2 = (lane&3)<<1;
    // fold deform bias + lrelu into acc
    #pragma unroll
    for (int nt=0;nt<8;nt++){
        int o = nt*8 + c2;
        float b0v = sBd[o], b1v = sBd[o+1];
        float v;
        v = acc[nt][0]+b0v; acc[nt][0] = v>=0.f?v:0.01f*v;
        v = acc[nt][1]+b1v; acc[nt][1] = v>=0.f?v:0.01f*v;
        v = acc[nt][2]+b0v; acc[nt][2] = v>=0.f?v:0.01f*v;
        v = acc[nt][3]+b1v; acc[nt][3] = v>=0.f?v:0.01f*v;
    }

    // residual 1x1 GEMM: K = 64 (one chunk)
    {
        #pragma unroll
        for (int g2=0; g2<4; g2++){
            union{ __half h[8]; uint4 u; } buf;
            #pragma unroll
            for (int j=0;j<8;j++){
                int c = cg*32 + g2*8 + j;
                buf.h[j] = __float2half(__ldg(xf + c*PLANE + base_p + n));
            }
            int seg = cg*4 + g2;
            *(uint4*)(SA + n*128 + ((seg ^ (n&7))<<4)) = buf.u;
        }
        {
            int o = tid>>2, part = tid&3;
            const uint4* srcp = (const uint4*)(g_Wrh + o*64 + part*16);
            uint4 v0 = srcp[0], v1 = srcp[1];
            int s0 = part*2;
            *(uint4*)(SB + o*128 + ((s0 ^ (o&7))<<4)) = v0;
            *(uint4*)(SB + o*128 + (((s0+1) ^ (o&7))<<4)) = v1;
        }
        __syncthreads();
        gemm_chunk(Ab, Bb, m0, lane, acc);
        __syncthreads();
    }

    // epilogue: + br, transpose, coalesced float4 stores
    float* sOut = (float*)(sm + 1024);
    #pragma unroll
    for (int nt=0;nt<8;nt++){
        int o = nt*8 + c2, nn = m0+q;
        float b0v = sBr[o], b1v = sBr[o+1];
        sOut[o*132+nn]       = acc[nt][0]+b0v;
        sOut[(o+1)*132+nn]   = acc[nt][1]+b1v;
        sOut[o*132+nn+8]     = acc[nt][2]+b0v;
        sOut[(o+1)*132+nn+8] = acc[nt][3]+b1v;
    }
    __syncthreads();
    int n4 = (tid&31)*4;
    #pragma unroll
    for (int i=0;i<8;i++){
        int o = (tid>>5) + i*8;
        float4 v = *(float4*)&sOut[o*132+n4];
        *(float4*)&out[o*PLANE + base_p + n4] = v;
    }
}

// -------- launch --------
extern "C" void kernel_launch(void* const* d_in, const int* in_sizes, int n_in,
                              void* d_out, int out_size) {
    (void)in_sizes; (void)n_in; (void)out_size;
    const float* x    = (const float*)d_in[0];
    const float* W1   = (const float*)d_in[1];
    const float* b1   = (const float*)d_in[2];
    const float* Woff = (const float*)d_in[3];
    const float* boff = (const float*)d_in[4];
    const float* Wd   = (const float*)d_in[5];
    const float* bd   = (const float*)d_in[6];
    const float* Wr   = (const float*)d_in[7];
    const float* br   = (const float*)d_in[8];
    float* out = (float*)d_out;

    cudaFuncSetAttribute(conv_f16<0>, cudaFuncAttributeMaxDynamicSharedMemorySize, SMEM_CONV);
    cudaFuncSetAttribute(conv_f16<1>, cudaFuncAttributeMaxDynamicSharedMemorySize, SMEM_CONV);
    cudaFuncSetAttribute(deform_f16,  cudaFuncAttributeMaxDynamicSharedMemorySize, SMEM_DEF);

    prep_weights<<<(KTAP*64*64 + 255)/256, 256>>>(W1, Woff, Wd, Wr);
    conv_f16<0><<<256, 256, SMEM_CONV>>>(x, b1);
    conv_f16<1><<<256, 256, SMEM_CONV>>>(x, boff);
    deform_f16<<<256, 256, SMEM_DEF>>>(x, bd, br, out);
}

// round 6
// speedup vs baseline: 8.7931x; 1.4463x over previous
#include <cuda_runtime.h>
#include <cuda_fp16.h>
#include <cstdint>

#define TT 8
#define HH 64
#define WWD 64
#define HWX 4096
#define PLANE 32768
#define KTAP 27

// -------- device scratch --------
__device__ __half g_xh[64*PLANE];        // x fp16, [pos][c]
__device__ __half g_y1h[64*PLANE];       // lrelu(conv1) fp16, [pos][c]
__device__ float  g_off[54*PLANE];       // offsets fp32, [o][pos]
__device__ __half g_W1h[KTAP*64*64];     // [tap][o][c]
__device__ __half g_Woffh[KTAP*64*64];
__device__ __half g_Wdh[KTAP*64*64];
__device__ __half g_Wrh[64*64];          // [o][c]

__device__ __forceinline__ uint32_t smem_u32(const void* p){
    uint32_t a;
    asm("{ .reg .u64 t; cvta.to.shared.u64 t, %1; cvt.u32.u64 %0, t; }"
        : "=r"(a) : "l"(p));
    return a;
}
__device__ __forceinline__ void ldsm4(uint32_t& r0,uint32_t& r1,uint32_t& r2,uint32_t& r3, uint32_t addr){
    asm volatile("ldmatrix.sync.aligned.m8n8.x4.shared.b16 {%0,%1,%2,%3}, [%4];"
        : "=r"(r0),"=r"(r1),"=r"(r2),"=r"(r3) : "r"(addr));
}
__device__ __forceinline__ void mma16816(float* d, uint32_t a0,uint32_t a1,uint32_t a2,uint32_t a3,
                                         uint32_t b0,uint32_t b1){
    asm volatile("mma.sync.aligned.m16n8k16.row.col.f32.f16.f16.f32 "
        "{%0,%1,%2,%3},{%4,%5,%6,%7},{%8,%9},{%0,%1,%2,%3};"
        : "+f"(d[0]),"+f"(d[1]),"+f"(d[2]),"+f"(d[3])
        : "r"(a0),"r"(a1),"r"(a2),"r"(a3),"r"(b0),"r"(b1));
}

// half (2 of 4 k-stages) of one K=64 chunk: A[128x64h] x B[64x64h]^T
template<int ST0>
__device__ __forceinline__ void gemm_half(uint32_t Ab, uint32_t Bb, int m0, int lane, float acc[8][4]){
    int g = lane>>3, r = lane&7;
    #pragma unroll
    for (int s=0;s<2;s++){
        int st = ST0 + s;
        int rowA = m0 + (g&1)*8 + r;
        int segA = st*2 + (g>>1);
        uint32_t a0,a1,a2,a3;
        ldsm4(a0,a1,a2,a3, Ab + rowA*128 + ((segA ^ (rowA&7))<<4));
        #pragma unroll
        for (int p=0;p<4;p++){
            int rowB = p*16 + (g>>1)*8 + r;
            int segB = st*2 + (g&1);
            uint32_t b0,b1,b2,b3;
            ldsm4(b0,b1,b2,b3, Bb + rowB*128 + ((segB ^ (rowB&7))<<4));
            mma16816(acc[2*p],   a0,a1,a2,a3, b0,b1);
            mma16816(acc[2*p+1], a0,a1,a2,a3, b2,b3);
        }
    }
}

__device__ __forceinline__ uint4 bilin8(const uint4* P, const float* W){
    uint4 r;
    const uint32_t* p0 = (const uint32_t*)&P[0];
    const uint32_t* p1 = (const uint32_t*)&P[1];
    const uint32_t* p2 = (const uint32_t*)&P[2];
    const uint32_t* p3 = (const uint32_t*)&P[3];
    uint32_t* ro = (uint32_t*)&r;
    #pragma unroll
    for (int k=0;k<4;k++){
        float2 f0 = __half22float2(*(const __half2*)&p0[k]);
        float2 f1 = __half22float2(*(const __half2*)&p1[k]);
        float2 f2 = __half22float2(*(const __half2*)&p2[k]);
        float2 f3 = __half22float2(*(const __half2*)&p3[k]);
        float vx = W[0]*f0.x + W[1]*f1.x + W[2]*f2.x + W[3]*f3.x;
        float vy = W[0]*f0.y + W[1]*f1.y + W[2]*f2.y + W[3]*f3.y;
        __half2 h = __floats2half2_rn(vx, vy);
        ro[k] = *(uint32_t*)&h;
    }
    return r;
}

// -------- prep: weights + x transpose --------
__global__ void prep_weights(const float* __restrict__ W1, const float* __restrict__ Woff,
                             const float* __restrict__ Wd, const float* __restrict__ Wr){
    int i = blockIdx.x*256 + threadIdx.x;
    if (i < KTAP*64*64){
        int tap = i>>12, o = (i>>6)&63, c = i&63;
        int src = o*1728 + c*27 + tap;
        g_W1h[i] = __float2half(W1[src]);
        g_Wdh[i] = __float2half(Wd[src]);
        g_Woffh[i] = (o < 54) ? __float2half(Woff[src]) : __half(0.f);
        if (i < 64*64) g_Wrh[i] = __float2half(Wr[i]);
    }
}

__global__ void prep_x(const float* __restrict__ x){
    __shared__ __half sT[128*72];
    int tid = threadIdx.x;
    int pos0 = blockIdx.x*128;
    int p = tid & 127, ch0 = tid >> 7;
    #pragma unroll 8
    for (int cc = 0; cc < 32; cc++){
        int c = cc*2 + ch0;
        sT[p*72 + c] = __float2half(x[c*PLANE + pos0 + p]);
    }
    __syncthreads();
    int oc = tid & 7;
    #pragma unroll
    for (int j = 0; j < 4; j++){
        int n = (tid>>3) + j*32;
        uint4 v = *(uint4*)&sT[n*72 + oc*8];
        *(uint4*)&g_xh[(pos0+n)*64 + oc*8] = v;
    }
}

// ==================== conv 3x3x3, fp16 mma, [pos][c] source ====================
// smem: misc 1024 | SA 16KB @1024 | SB 8KB @17408 ; epilogue aliases @1024
#define SMEM_CONV 34816
template<int MODE>   // 0: xh -> y1h (lrelu); 1: y1h -> g_off (54 ch)
__global__ void __launch_bounds__(256)
conv_f16(const float* __restrict__ bias)
{
    extern __shared__ char sm[];
    float* sBias = (float*)sm;
    char* SA = sm + 1024;
    char* SB = sm + 17408;
    uint32_t sbase = smem_u32(sm);
    uint32_t Ab = sbase + 1024, Bb = sbase + 17408;
    const __half* src  = (MODE==0)? g_xh  : g_y1h;
    const __half* Wall = (MODE==0)? g_W1h : g_Woffh;

    int tid = threadIdx.x, lane = tid&31, wid = tid>>5;
    int t = blockIdx.x>>5, h0 = (blockIdx.x&31)<<1;
    if (tid < 64) sBias[tid] = (MODE==0 || tid<54)? bias[tid] : 0.f;
    __syncthreads();

    int oc = tid&7;
    int m0 = wid*16;
    float acc[8][4];
    #pragma unroll
    for (int i=0;i<8;i++){ acc[i][0]=0.f; acc[i][1]=0.f; acc[i][2]=0.f; acc[i][3]=0.f; }

    for (int tap=0; tap<KTAP; tap++){
        int kt=tap/9, rr=tap-kt*9, kh=rr/3, kw=rr-kh*3;
        int t_in = t-1+kt;
        #pragma unroll
        for (int j=0;j<4;j++){
            int n = (tid>>3) + j*32;
            int hh = n>>6, w = n&63;
            int h_in = h0+hh-1+kh, w_in = w-1+kw;
            bool valid = ((unsigned)t_in<TT)&&((unsigned)h_in<HH)&&((unsigned)w_in<WWD);
            uint4 v = make_uint4(0,0,0,0);
            if (valid) v = *(const uint4*)&src[(t_in*HWX + h_in*WWD + w_in)*64 + oc*8];
            *(uint4*)(SA + n*128 + ((oc ^ (n&7))<<4)) = v;
        }
        {
            int o = tid>>2, part = tid&3;
            const uint4* sp = (const uint4*)(Wall + tap*4096 + o*64 + part*16);
            uint4 v0 = sp[0], v1 = sp[1];
            int s0 = part*2;
            *(uint4*)(SB + o*128 + ((s0 ^ (o&7))<<4)) = v0;
            *(uint4*)(SB + o*128 + (((s0+1)^(o&7))<<4)) = v1;
        }
        __syncthreads();
        gemm_half<0>(Ab,Bb,m0,lane,acc);
        gemm_half<2>(Ab,Bb,m0,lane,acc);
        __syncthreads();
    }

    int q = lane>>2, c2 = (lane&3)<<1;
    int base = t*HWX + h0*WWD;
    if (MODE==0){
        __half* sOutH = (__half*)(sm + 1024);  // [n][72]
        #pragma unroll
        for (int nt=0;nt<8;nt++){
            int o = nt*8 + c2, nn = m0+q;
            float b0v = sBias[o], b1v = sBias[o+1];
            float v0 = acc[nt][0]+b0v, v1 = acc[nt][1]+b1v;
            float v2 = acc[nt][2]+b0v, v3 = acc[nt][3]+b1v;
            v0 = v0>=0.f?v0:0.01f*v0; v1 = v1>=0.f?v1:0.01f*v1;
            v2 = v2>=0.f?v2:0.01f*v2; v3 = v3>=0.f?v3:0.01f*v3;
            sOutH[nn*72 + o]       = __float2half(v0);
            sOutH[nn*72 + o+1]     = __float2half(v1);
            sOutH[(nn+8)*72 + o]   = __float2half(v2);
            sOutH[(nn+8)*72 + o+1] = __float2half(v3);
        }
        __syncthreads();
        #pragma unroll
        for (int j=0;j<4;j++){
            int n = (tid>>3) + j*32;
            uint4 v = *(uint4*)&sOutH[n*72 + oc*8];
            *(uint4*)&g_y1h[(base+n)*64 + oc*8] = v;
        }
    } else {
        float* sOut = (float*)(sm + 1024);     // [o][132]
        #pragma unroll
        for (int nt=0;nt<8;nt++){
            int o = nt*8 + c2, nn = m0+q;
            float b0v = sBias[o], b1v = sBias[o+1];
            sOut[o*132+nn]       = acc[nt][0]+b0v;
            sOut[(o+1)*132+nn]   = acc[nt][1]+b1v;
            sOut[o*132+nn+8]     = acc[nt][2]+b0v;
            sOut[(o+1)*132+nn+8] = acc[nt][3]+b1v;
        }
        __syncthreads();
        int n4 = (tid&31)*4;
        #pragma unroll
        for (int i=0;i<8;i++){
            int o = (tid>>5) + i*8;
            if (o < 54){
                float4 v = *(float4*)&sOut[o*132+n4];
                *(float4*)&g_off[o*PLANE + base + n4] = v;
            }
        }
    }
}

// ==================== deformable conv + residual + lrelu, pipelined ====================
// smem: misc[0,1024) | SA0[1024,17408) | SA1[17408,33792) | SB0[33792,41984) |
//       SB1[41984,50176) | tab[50176,77824) ; fp32 sOut aliases @17408
#define SMEM_DEF 77824

__device__ __forceinline__ void dledg(int tap, int tid, const uint2* sTab,
                                      uint4 P[2][4], float W[2][4], int j0){
    int oc = tid&7;
    #pragma unroll
    for (int jj=0;jj<2;jj++){
        int n = (tid>>3) + (j0+jj)*32;
        uint2 tb = sTab[tap*128 + n];
        uint32_t pk = tb.x;
        __half2 fhw = *(__half2*)&tb.y;
        float fh = __low2float(fhw), fw = __high2float(fhw);
        int wb = (int)(pk&127)-2, hb = (int)((pk>>7)&127)-2;
        int tc = (int)((pk>>14)&7);
        unsigned mask = pk>>17;
        float w00=(1.f-fh)*(1.f-fw), w01=(1.f-fh)*fw, w10=fh*(1.f-fw), w11=fh*fw;
        if(!(mask&1u)) w00=0.f;
        if(!(mask&2u)) w01=0.f;
        if(!(mask&4u)) w10=0.f;
        if(!(mask&8u)) w11=0.f;
        int ih0=min(max(hb,0),HH-1),  ih1=min(max(hb+1,0),HH-1);
        int iw0=min(max(wb,0),WWD-1), iw1=min(max(wb+1,0),WWD-1);
        int b0 = tc*HWX;
        P[jj][0] = *(const uint4*)&g_y1h[(b0+ih0*WWD+iw0)*64 + oc*8];
        P[jj][1] = *(const uint4*)&g_y1h[(b0+ih0*WWD+iw1)*64 + oc*8];
        P[jj][2] = *(const uint4*)&g_y1h[(b0+ih1*WWD+iw0)*64 + oc*8];
        P[jj][3] = *(const uint4*)&g_y1h[(b0+ih1*WWD+iw1)*64 + oc*8];
        W[jj][0]=w00; W[jj][1]=w01; W[jj][2]=w10; W[jj][3]=w11;
    }
}
__device__ __forceinline__ void rledg(int tid, int base_p, uint4 P[2][4], float W[2][4], int j0){
    int oc = tid&7;
    #pragma unroll
    for (int jj=0;jj<2;jj++){
        int n = (tid>>3) + (j0+jj)*32;
        P[jj][0] = *(const uint4*)&g_xh[(base_p+n)*64 + oc*8];
        P[jj][1] = make_uint4(0,0,0,0);
        P[jj][2] = make_uint4(0,0,0,0);
        P[jj][3] = make_uint4(0,0,0,0);
        W[jj][0]=1.f; W[jj][1]=0.f; W[jj][2]=0.f; W[jj][3]=0.f;
    }
}
__device__ __forceinline__ void dlsts(char* SA, int tid, uint4 P[2][4], float W[2][4], int j0){
    int oc = tid&7;
    #pragma unroll
    for (int jj=0;jj<2;jj++){
        int n = (tid>>3) + (j0+jj)*32;
        uint4 r = bilin8(P[jj], W[jj]);
        *(uint4*)(SA + n*128 + ((oc ^ (n&7))<<4)) = r;
    }
}

__global__ void __launch_bounds__(256)
deform_f16(const float* __restrict__ bd, const float* __restrict__ br,
           float* __restrict__ out)
{
    extern __shared__ char sm[];
    float* sBd = (float*)sm;
    float* sBr = (float*)(sm + 256);
    char* SA0 = sm + 1024;
    char* SA1 = sm + 17408;
    char* SB0 = sm + 33792;
    char* SB1 = sm + 41984;
    uint2* sTab = (uint2*)(sm + 50176);
    uint32_t sbase = smem_u32(sm);

    int tid = threadIdx.x, lane = tid&31, wid = tid>>5;
    int t = blockIdx.x>>5, h0 = (blockIdx.x&31)<<1;
    if (tid < 64){ sBd[tid] = bd[tid]; sBr[tid] = br[tid]; }

    // bilinear tap table (8B per (tap,n)), computed once
    for (int e = tid; e < KTAP*128; e += 256){
        int tap = e>>7, n = e&127;
        int hh = n>>6, w = n&63;
        int h = h0 + hh;
        int kt = tap/9, rr = tap-kt*9, kh = rr/3, kw = rr-kh*3;
        int t_in = t-1+kt;
        bool t_ok = (unsigned)t_in < TT;
        int t_c = min(max(t_in,0),TT-1);
        int pidx = t*HWX + h*WWD + w;
        float dh = g_off[(2*tap)*PLANE + pidx];
        float dw = g_off[(2*tap+1)*PLANE + pidx];
        float h_s = (float)(h-1+kh)+dh, w_s = (float)(w-1+kw)+dw;
        float h0f = floorf(h_s), w0f = floorf(w_s);
        float fh = h_s-h0f, fw = w_s-w0f;
        int hb = (int)h0f, wb = (int)w0f;
        unsigned mask = 0;
        if (t_ok){
            unsigned h0ok = ((unsigned)hb < HH),  h1ok = ((unsigned)(hb+1) < HH);
            unsigned w0ok = ((unsigned)wb < WWD), w1ok = ((unsigned)(wb+1) < WWD);
            mask = (h0ok&w0ok) | ((h0ok&w1ok)<<1) | ((h1ok&w0ok)<<2) | ((h1ok&w1ok)<<3);
        }
        int hbc = min(max(hb,-2),64), wbc = min(max(wb,-2),64);
        uint32_t pack = (uint32_t)(wbc+2) | ((uint32_t)(hbc+2)<<7) | ((uint32_t)t_c<<14) | (mask<<17);
        __half2 f2 = __floats2half2_rn(fh, fw);
        sTab[e] = make_uint2(pack, *(uint32_t*)&f2);
    }
    __syncthreads();

    int m0 = wid*16;
    int base_p = t*HWX + h0*WWD;
    float acc[8][4];
    #pragma unroll
    for (int i=0;i<8;i++){ acc[i][0]=0.f; acc[i][1]=0.f; acc[i][2]=0.f; acc[i][3]=0.f; }

    int o_w = tid>>2, part = tid&3, s0w = part*2;

    // prologue: stage chunk 0 into buffer 0
    {
        uint4 P[2][4]; float W[2][4];
        dledg(0, tid, sTab, P, W, 0); dlsts(SA0, tid, P, W, 0);
        dledg(0, tid, sTab, P, W, 2); dlsts(SA0, tid, P, W, 2);
        const uint4* sp = (const uint4*)(g_Wdh + o_w*64 + part*16);
        uint4 wv0 = sp[0], wv1 = sp[1];
        *(uint4*)(SB0 + o_w*128 + ((s0w ^ (o_w&7))<<4)) = wv0;
        *(uint4*)(SB0 + o_w*128 + (((s0w+1)^(o_w&7))<<4)) = wv1;
    }
    __syncthreads();

    // 28 chunks: taps 0..26 + residual
    for (int it = 0; it < 28; it++){
        int p = it & 1;
        uint32_t Abc = sbase + (p ? 17408 : 1024);
        uint32_t Bbc = sbase + (p ? 41984 : 33792);
        char* SAn = p ? SA0 : SA1;
        char* SBn = p ? SB0 : SB1;
        int nxt = it + 1;
        bool more = nxt < 28;

        uint4 P[2][4]; float W[2][4];
        uint4 wv0, wv1;
        if (more){
            if (nxt < 27) dledg(nxt, tid, sTab, P, W, 0);
            else          rledg(tid, base_p, P, W, 0);
            const __half* Wsrc = (nxt < 27) ? (g_Wdh + nxt*4096) : g_Wrh;
            const uint4* sp = (const uint4*)(Wsrc + o_w*64 + part*16);
            wv0 = sp[0]; wv1 = sp[1];
        }
        gemm_half<0>(Abc, Bbc, m0, lane, acc);
        if (more){
            dlsts(SAn, tid, P, W, 0);
            if (nxt < 27) dledg(nxt, tid, sTab, P, W, 2);
            else          rledg(tid, base_p, P, W, 2);
        }
        gemm_half<2>(Abc, Bbc, m0, lane, acc);
        if (more){
            dlsts(SAn, tid, P, W, 2);
            *(uint4*)(SBn + o_w*128 + ((s0w ^ (o_w&7))<<4)) = wv0;
            *(uint4*)(SBn + o_w*128 + (((s0w+1)^(o_w&7))<<4)) = wv1;
        }
        if (it == 26){
            int c2f = (lane&3)<<1;
            #pragma unroll
            for (int nt=0;nt<8;nt++){
                int o = nt*8 + c2f;
                float b0v = sBd[o], b1v = sBd[o+1];
                float v;
                v = acc[nt][0]+b0v; acc[nt][0] = v>=0.f?v:0.01f*v;
                v = acc[nt][1]+b1v; acc[nt][1] = v>=0.f?v:0.01f*v;
                v = acc[nt][2]+b0v; acc[nt][2] = v>=0.f?v:0.01f*v;
                v = acc[nt][3]+b1v; acc[nt][3] = v>=0.f?v:0.01f*v;
            }
        }
        __syncthreads();
    }

    // epilogue: + br, transpose, coalesced float4 stores
    int q = lane>>2, c2 = (lane&3)<<1;
    float* sOut = (float*)(sm + 17408);   // [o][132]
    #pragma unroll
    for (int nt=0;nt<8;nt++){
        int o = nt*8 + c2, nn = m0+q;
        float b0v = sBr[o], b1v = sBr[o+1];
        sOut[o*132+nn]       = acc[nt][0]+b0v;
        sOut[(o+1)*132+nn]   = acc[nt][1]+b1v;
        sOut[o*132+nn+8]     = acc[nt][2]+b0v;
        sOut[(o+1)*132+nn+8] = acc[nt][3]+b1v;
    }
    __syncthreads();
    int n4 = (tid&31)*4;
    #pragma unroll
    for (int i=0;i<8;i++){
        int o = (tid>>5) + i*8;
        float4 v = *(float4*)&sOut[o*132+n4];
        *(float4*)&out[o*PLANE + base_p + n4] = v;
    }
}

// -------- launch --------
extern "C" void kernel_launch(void* const* d_in, const int* in_sizes, int n_in,
                              void* d_out, int out_size) {
    (void)in_sizes; (void)n_in; (void)out_size;
    const float* x    = (const float*)d_in[0];
    const float* W1   = (const float*)d_in[1];
    const float* b1   = (const float*)d_in[2];
    const float* Woff = (const float*)d_in[3];
    const float* boff = (const float*)d_in[4];
    const float* Wd   = (const float*)d_in[5];
    const float* bd   = (const float*)d_in[6];
    const float* Wr   = (const float*)d_in[7];
    const float* br   = (const float*)d_in[8];
    float* out = (float*)d_out;

    cudaFuncSetAttribute(conv_f16<0>, cudaFuncAttributeMaxDynamicSharedMemorySize, SMEM_CONV);
    cudaFuncSetAttribute(conv_f16<1>, cudaFuncAttributeMaxDynamicSharedMemorySize, SMEM_CONV);
    cudaFuncSetAttribute(deform_f16,  cudaFuncAttributeMaxDynamicSharedMemorySize, SMEM_DEF);

    prep_weights<<<(KTAP*64*64 + 255)/256, 256>>>(W1, Woff, Wd, Wr);
    prep_x<<<256, 256>>>(x);
    conv_f16<0><<<256, 256, SMEM_CONV>>>(b1);
    conv_f16<1><<<256, 256, SMEM_CONV>>>(boff);
    deform_f16<<<256, 256, SMEM_DEF>>>(bd, br, out);
}